// round 14
// baseline (speedup 1.0000x reference)
#include <cuda_runtime.h>
#include <cuda_fp16.h>
#include <math.h>
#include <stdint.h>

#define NROWS 131072
#define DDIM  64
#define KCODE 512

// ---- dynamic smem byte offsets for k_main ----
// planes padded to 72 halves (144 B) per row -> 4-bank shift per row/col
#define OFF_AH  0           // 128 rows x 144B
#define OFF_AL  18432
#define OFF_BH  36864       // 128 codes x 144B (one chunk)
#define OFF_BL  55296
#define OFF_EN  73728       // float[512] (0.5*||e||^2)
#define OFF_IDX 75776       // int[128]
#define SMEM_DYN 76288

// ---- static device scratch ----
__device__ __align__(16) __half g_Bh[KCODE * DDIM];   // codebook hi plane
__device__ __align__(16) __half g_Bl[KCODE * DDIM];   // codebook lo' plane
__device__ float  g_en2[KCODE];                       // 0.5*||e||^2
__device__ __align__(16) float g_dw[KCODE * DDIM];
__device__ int    g_counts[KCODE];
__device__ int    g_idx[NROWS];
__device__ float  g_loss;
__device__ int    g_done;

// ---- helpers ----
__device__ __forceinline__ uint32_t smem_u32(const void* p) {
    uint32_t a;
    asm("{ .reg .u64 t; cvta.to.shared.u64 t, %1; cvt.u32.u64 %0, t; }"
        : "=r"(a) : "l"(p));
    return a;
}
__device__ __forceinline__ void split2h(float a, __half& hi, __half& lo) {
    hi = __float2half_rn(a);
    float r = a - __half2float(hi);      // exact
    lo = __float2half_rn(r * 2048.0f);   // scaled residual, avoids subnormals
}
__device__ __forceinline__ void mma16(float c[4], const uint32_t a[4],
                                      uint32_t b0, uint32_t b1) {
    asm volatile("mma.sync.aligned.m16n8k16.row.col.f32.f16.f16.f32 "
                 "{%0,%1,%2,%3}, {%4,%5,%6,%7}, {%8,%9}, {%0,%1,%2,%3};"
                 : "+f"(c[0]), "+f"(c[1]), "+f"(c[2]), "+f"(c[3])
                 : "r"(a[0]), "r"(a[1]), "r"(a[2]), "r"(a[3]),
                   "r"(b0), "r"(b1));
}
__device__ __forceinline__ void ldsm4(uint32_t& r0, uint32_t& r1,
                                      uint32_t& r2, uint32_t& r3, uint32_t addr) {
    asm volatile("ldmatrix.sync.aligned.m8n8.x4.shared.b16 {%0,%1,%2,%3}, [%4];"
                 : "=r"(r0), "=r"(r1), "=r"(r2), "=r"(r3) : "r"(addr));
}

// ---------------------------------------------------------------------------
// k_init: fused zero + codebook split + norms. grid 64 x 512.
// ---------------------------------------------------------------------------
__global__ void k_init(const float* __restrict__ emb)
{
    const int t = threadIdx.x;
    const int gid = blockIdx.x * 512 + t;
    float a = emb[gid];
    __half hi, lo;
    split2h(a, hi, lo);
    g_Bh[gid] = hi;
    g_Bl[gid] = lo;
    g_dw[gid] = 0.0f;
    if (blockIdx.x == 0) {
        g_counts[t] = 0;
        const float4* e4 = (const float4*)(emb + t * DDIM);
        float s = 0.0f;
#pragma unroll
        for (int i = 0; i < 16; i++) {
            float4 v = e4[i];
            s += v.x * v.x + v.y * v.y + v.z * v.z + v.w * v.w;
        }
        g_en2[t] = 0.5f * s;
        if (t == 0) { g_loss = 0.0f; g_done = 0; }
    }
}

// ---------------------------------------------------------------------------
// k_main: 3-product double-fp16 m16n8k16 + argmin + fused one-hot + dw.
// grid 1024 x 256, 2 blocks/SM. Block: 128 rows x 512 codes, K = 64.
// B fragments double-buffered across the 16 column-steps of each chunk.
// Enc zero-fill issued up-front so DRAM drains during the mma phase.
// argmin over s = 0.5*||e||^2 - dot   (monotone transform of reference score)
// ---------------------------------------------------------------------------
__global__ void __launch_bounds__(256, 2) k_main(const float* __restrict__ flat,
                                                 float* __restrict__ enc)
{
    extern __shared__ __align__(16) unsigned char smx[];
    float* sEn2 = (float*)(smx + OFF_EN);
    int*   sIdx = (int*)(smx + OFF_IDX);

    const int tid  = threadIdx.x;
    const int lane = tid & 31;
    const int w    = tid >> 5;
    const int n0   = blockIdx.x * 128;
    const uint32_t sbase = smem_u32(smx);

    // ---- A fill: fp32 -> (hi, lo') fp16 planes ----
    {
        const float2* f2 = (const float2*)(flat + (size_t)n0 * DDIM);
#pragma unroll
        for (int it = 0; it < 16; it++) {
            int i = it * 256 + tid;          // 4096 half2-slots (128 rows x 32)
            int row = i >> 5, j = i & 31;
            float2 a = f2[i];
            __half hx, lx, hy, ly;
            split2h(a.x, hx, lx);
            split2h(a.y, hy, ly);
            __half2 h; h.x = hx; h.y = hy;
            *(__half2*)(smx + OFF_AH + row * 144 + j * 4) = h;
            h.x = lx; h.y = ly;
            *(__half2*)(smx + OFF_AL + row * 144 + j * 4) = h;
        }
    }

    // ---- early encodings zero-fill: stores drain while we compute ----
    {
        float2* eb = (float2*)(enc + (size_t)n0 * KCODE);
        const float2 z = make_float2(0.0f, 0.0f);
#pragma unroll 8
        for (int it = 0; it < 128; it++)
            eb[it * 256 + tid] = z;          // 32768 float2 = 128 rows x 512
    }

    for (int i = tid; i < KCODE; i += 256) sEn2[i] = g_en2[i];
    __syncthreads();

    // ---- A fragment preload (register-resident): 4 k-steps of 16 ----
    const int r0 = w * 16 + (lane >> 2);
    uint32_t ah[4][4], al[4][4];
#pragma unroll
    for (int ks = 0; ks < 4; ks++) {
        int kb2 = (ks * 16 + (lane & 3) * 2) * 2;   // byte offset within row
        ah[ks][0] = *(const uint32_t*)(smx + OFF_AH + r0 * 144 + kb2);
        ah[ks][1] = *(const uint32_t*)(smx + OFF_AH + (r0 + 8) * 144 + kb2);
        ah[ks][2] = *(const uint32_t*)(smx + OFF_AH + r0 * 144 + kb2 + 16);
        ah[ks][3] = *(const uint32_t*)(smx + OFF_AH + (r0 + 8) * 144 + kb2 + 16);
        al[ks][0] = *(const uint32_t*)(smx + OFF_AL + r0 * 144 + kb2);
        al[ks][1] = *(const uint32_t*)(smx + OFF_AL + (r0 + 8) * 144 + kb2);
        al[ks][2] = *(const uint32_t*)(smx + OFF_AL + r0 * 144 + kb2 + 16);
        al[ks][3] = *(const uint32_t*)(smx + OFF_AL + (r0 + 8) * 144 + kb2 + 16);
    }
    float mn0 = 3.402823466e38f, mn1 = 3.402823466e38f;
    int   mi0 = 0, mi1 = 0;

    const float C1 = 4.8828125e-4f;          // 2^-11

    // per-thread ldmatrix base: code row = lane&7 (stride 144B), kseg = lane>>3
    const uint32_t lmOff = (uint32_t)((lane & 7) * 144 + (lane >> 3) * 16);
    const uint32_t bHbase = sbase + OFF_BH + lmOff;
    const uint32_t bLbase = sbase + OFF_BL + lmOff;

    // ---- main loop: 4 chunks of 128 codes ----
#pragma unroll 1
    for (int c = 0; c < 4; c++) {
        // B chunk fill: 8B copies, padded stride 144B
        {
            const uint2* sh = (const uint2*)(g_Bh + (size_t)c * 128 * 64);
            const uint2* sl = (const uint2*)(g_Bl + (size_t)c * 128 * 64);
#pragma unroll
            for (int it = 0; it < 8; it++) {
                int i = it * 256 + tid;       // 2048 x 8B per plane
                int code = i >> 4, j = i & 15;
                *(uint2*)(smx + OFF_BH + code * 144 + j * 8) = sh[i];
                *(uint2*)(smx + OFF_BL + code * 144 + j * 8) = sl[i];
            }
        }
        __syncthreads();

        // double-buffered B fragments over 16 column-steps (8 codes each)
        uint32_t bh[2][4][2], bl[2][4][2];
        ldsm4(bh[0][0][0], bh[0][0][1], bh[0][1][0], bh[0][1][1], bHbase);
        ldsm4(bh[0][2][0], bh[0][2][1], bh[0][3][0], bh[0][3][1], bHbase + 64);
        ldsm4(bl[0][0][0], bl[0][0][1], bl[0][1][0], bl[0][1][1], bLbase);
        ldsm4(bl[0][2][0], bl[0][2][1], bl[0][3][0], bl[0][3][1], bLbase + 64);

#pragma unroll
        for (int s16 = 0; s16 < 16; s16++) {
            const int cur = s16 & 1, nxt = cur ^ 1;
            if (s16 < 15) {
                const uint32_t nOff = (uint32_t)((s16 + 1) * 1152);  // 8*144
                ldsm4(bh[nxt][0][0], bh[nxt][0][1], bh[nxt][1][0], bh[nxt][1][1],
                      bHbase + nOff);
                ldsm4(bh[nxt][2][0], bh[nxt][2][1], bh[nxt][3][0], bh[nxt][3][1],
                      bHbase + nOff + 64);
                ldsm4(bl[nxt][0][0], bl[nxt][0][1], bl[nxt][1][0], bl[nxt][1][1],
                      bLbase + nOff);
                ldsm4(bl[nxt][2][0], bl[nxt][2][1], bl[nxt][3][0], bl[nxt][3][1],
                      bLbase + nOff + 64);
            }

            float hh[4], m0[4], m1[4];
#pragma unroll
            for (int i = 0; i < 4; i++) { hh[i] = 0.0f; m0[i] = 0.0f; m1[i] = 0.0f; }
#pragma unroll
            for (int ks = 0; ks < 4; ks++) {
                mma16(hh, ah[ks], bh[cur][ks][0], bh[cur][ks][1]);  // hi*hi   (1)
                mma16(m0, ah[ks], bl[cur][ks][0], bl[cur][ks][1]);  // hi*lo'  (2^-11)
                mma16(m1, al[ks], bh[cur][ks][0], bh[cur][ks][1]);  // lo'*hi  (2^-11)
            }

            // epilogue: s = 0.5||e||^2 - dot ; fold into running argmin
            const int cb = c * 128 + s16 * 8 + (lane & 3) * 2;
#pragma unroll
            for (int i = 0; i < 4; i++) {
                float dot = fmaf(C1, m0[i] + m1[i], hh[i]);
                int col = cb + (i & 1);
                float s = __fsub_rn(sEn2[col], dot);
                if (i < 2) { if (s < mn0) { mn0 = s; mi0 = col; } }
                else       { if (s < mn1) { mn1 = s; mi1 = col; } }
            }
        }
        __syncthreads();   // done reading this B chunk
    }

    // ---- cross-lane argmin reduce (4 threads share each row) ----
#pragma unroll
    for (int off = 1; off < 4; off <<= 1) {
        float om = __shfl_xor_sync(0xffffffffu, mn0, off);
        int   oi = __shfl_xor_sync(0xffffffffu, mi0, off);
        if (om < mn0 || (om == mn0 && oi < mi0)) { mn0 = om; mi0 = oi; }
        om = __shfl_xor_sync(0xffffffffu, mn1, off);
        oi = __shfl_xor_sync(0xffffffffu, mi1, off);
        if (om < mn1 || (om == mn1 && oi < mi1)) { mn1 = om; mi1 = oi; }
    }
    if ((lane & 3) == 0) {
        g_idx[n0 + r0] = mi0;     sIdx[r0] = mi0;
        g_idx[n0 + r0 + 8] = mi1; sIdx[r0 + 8] = mi1;
        atomicAdd(&g_counts[mi0], 1);
        atomicAdd(&g_counts[mi1], 1);
    }
    __syncthreads();
    if (tid < 128)
        enc[(size_t)(n0 + tid) * KCODE + sIdx[tid]] = 1.0f;

    // ---- dw segment-sum scatter (coalesced reads, fp atomics) ----
    {
        const float* rowsG = flat + (size_t)n0 * DDIM;
#pragma unroll 4
        for (int it = 0; it < 32; it++) {
            int i = it * 256 + tid;          // 8192 elements
            int r = i >> 6, d = i & 63;
            atomicAdd(&g_dw[sIdx[r] * DDIM + d], rowsG[i]);
        }
    }
}

// ---------------------------------------------------------------------------
// k_quant: fused codebook-update + gather + NHWC->NCHW write + loss +
// perplexity (block 0) + final loss (last block).
// grid 1024 x 256. Block: 128 rows.
// Each block recomputes the 512-wide smoothed cluster sizes (cheap,
// deterministic) and builds new_emb values on the fly during the gather:
//     q = (ema_w*0.99 + 0.01*dw) / scs[code]
// ---------------------------------------------------------------------------
__global__ __launch_bounds__(256) void k_quant(const float* __restrict__ x,
                                               const float* __restrict__ ema_cs,
                                               const float* __restrict__ ema_w,
                                               float* __restrict__ outQ,
                                               float* __restrict__ outP,
                                               float* __restrict__ out0)
{
    __shared__ float q[128][65];
    __shared__ int   idxs[128];
    __shared__ float scs[512];
    __shared__ float red[512];
    __shared__ float wsum[8];
    const int t  = threadIdx.x;
    const int n0 = blockIdx.x * 128;
    if (t < 128) idxs[t] = g_idx[n0 + t];

    // ---- smoothed cluster sizes (2 codes per thread) ----
#pragma unroll
    for (int j = 0; j < 2; j++) {
        int k = t + j * 256;
        float c  = (float)g_counts[k];
        float cs = ema_cs[k] * 0.99f + 0.01f * c;
        red[k] = cs;
        scs[k] = cs;
    }
    __syncthreads();
    for (int s = 256; s; s >>= 1) { if (t < s) red[t] += red[t + s]; __syncthreads(); }
    const float nsum = red[0];
    __syncthreads();
#pragma unroll
    for (int j = 0; j < 2; j++) {
        int k = t + j * 256;
        scs[k] = (scs[k] + 1e-5f) / (nsum + 512.0f * 1e-5f) * nsum;
    }
    __syncthreads();

    // ---- gather + on-the-fly codebook update + loss partial ----
    float lsum = 0.0f;
    const float4* xb4 = (const float4*)(x + (size_t)n0 * DDIM);
    const float4* ew4 = (const float4*)ema_w;
    const float4* dw4 = (const float4*)g_dw;
#pragma unroll
    for (int it = 0; it < 8; it++) {
        int i = it * 256 + t;                // 2048 float4 = 128 rows x 16
        int r = i >> 4, dg = i & 15;
        int code = idxs[r];
        float4 wv = ew4[code * 16 + dg];
        float4 dv = dw4[code * 16 + dg];
        float s = scs[code];
        float4 qv;
        qv.x = (wv.x * 0.99f + 0.01f * dv.x) / s;
        qv.y = (wv.y * 0.99f + 0.01f * dv.y) / s;
        qv.z = (wv.z * 0.99f + 0.01f * dv.z) / s;
        qv.w = (wv.w * 0.99f + 0.01f * dv.w) / s;
        float4 xv = xb4[i];
        float dx = qv.x - xv.x, dy = qv.y - xv.y;
        float dz = qv.z - xv.z, dww = qv.w - xv.w;
        lsum = fmaf(dx, dx, lsum); lsum = fmaf(dy, dy, lsum);
        lsum = fmaf(dz, dz, lsum); lsum = fmaf(dww, dww, lsum);
        int d0 = dg << 2;
        q[r][d0] = qv.x; q[r][d0 + 1] = qv.y;
        q[r][d0 + 2] = qv.z; q[r][d0 + 3] = qv.w;
    }
    __syncthreads();

    // ---- NCHW write (rows within one batch image; 4096 rows/image) ----
    const int b   = n0 >> 12;
    const int loc = n0 & 4095;
    float* dst = outQ + (size_t)b * 262144 + loc;
#pragma unroll
    for (int it = 0; it < 32; it++) {
        int i = it * 256 + t;                // 8192 = 64 d x 128 n
        int d = i >> 7, n = i & 127;
        dst[d * 4096 + n] = q[n][d];         // smem (65n+d)%32 conflict-free
    }

    // ---- loss partial -> global atomic ----
#pragma unroll
    for (int o = 16; o; o >>= 1) lsum += __shfl_xor_sync(0xffffffffu, lsum, o);
    if ((t & 31) == 0) wsum[t >> 5] = lsum;
    __syncthreads();
    if (t == 0) {
        float s = 0.0f;
#pragma unroll
        for (int wv = 0; wv < 8; wv++) s += wsum[wv];
        atomicAdd(&g_loss, s);
    }

    // ---- perplexity (block 0 only) ----
    if (blockIdx.x == 0) {
#pragma unroll
        for (int j = 0; j < 2; j++) {
            int k = t + j * 256;
            float p = (float)g_counts[k] * (1.0f / 131072.0f);
            red[k] = p * logf(p + 1e-10f);
        }
        __syncthreads();
        for (int s = 256; s; s >>= 1) { if (t < s) red[t] += red[t + s]; __syncthreads(); }
        if (t == 0) outP[0] = expf(-red[0]);
    }

    // ---- final loss: last block to finish writes out[0] ----
    if (t == 0) {
        __threadfence();
        int old = atomicAdd(&g_done, 1);
        if (old == 1023) {
            __threadfence();
            float gl = *(volatile float*)&g_loss;
            out0[0] = 0.25f * gl * (1.0f / 8388608.0f);
        }
    }
}

// ---------------------------------------------------------------------------
// Output layout (float32): [0] loss | [1..8388609) quantized NCHW |
// [8388609] perplexity | [8388610..) encodings [131072, 512]
// ---------------------------------------------------------------------------
extern "C" void kernel_launch(void* const* d_in, const int* in_sizes, int n_in,
                              void* d_out, int out_size)
{
    const float* inputs = (const float*)d_in[0];
    const float* emb_w  = (const float*)d_in[1];
    const float* ema_cs = (const float*)d_in[2];
    const float* ema_w  = (const float*)d_in[3];
    float* out  = (float*)d_out;
    float* outQ = out + 1;
    float* outP = out + 1 + 8388608;
    float* outE = out + 2 + 8388608;

    cudaFuncSetAttribute(k_main, cudaFuncAttributeMaxDynamicSharedMemorySize, SMEM_DYN);

    k_init<<<64, 512>>>(emb_w);
    k_main<<<NROWS / 128, 256, SMEM_DYN>>>(inputs, outE);
    k_quant<<<NROWS / 128, 256>>>(inputs, ema_cs, ema_w, outQ, outP, out);
}

// round 15
// speedup vs baseline: 1.0287x; 1.0287x over previous
#include <cuda_runtime.h>
#include <cuda_fp16.h>
#include <math.h>
#include <stdint.h>

#define NROWS 131072
#define DDIM  64
#define KCODE 512

// ---- dynamic smem byte offsets for k_main ----
// planes padded to 72 halves (144 B) per row -> 4-bank shift per row/col
#define OFF_AH  0           // 128 rows x 144B
#define OFF_AL  18432
#define OFF_BH  36864       // 128 codes x 144B (one chunk)
#define OFF_BL  55296
#define OFF_EN  73728       // float[512] (0.5*||e||^2)
#define OFF_IDX 75776       // int[128]
#define SMEM_DYN 76288

// ---- static device scratch ----
__device__ __align__(16) __half g_Bh[KCODE * DDIM];   // codebook hi plane
__device__ __align__(16) __half g_Bl[KCODE * DDIM];   // codebook lo' plane
__device__ float  g_en2[KCODE];                       // 0.5*||e||^2
__device__ __align__(16) float g_dw[KCODE * DDIM];
__device__ int    g_counts[KCODE];
__device__ __align__(16) float g_new_emb[KCODE * DDIM];
__device__ int    g_idx[NROWS];
__device__ float  g_loss;

// ---- helpers ----
__device__ __forceinline__ uint32_t smem_u32(const void* p) {
    uint32_t a;
    asm("{ .reg .u64 t; cvta.to.shared.u64 t, %1; cvt.u32.u64 %0, t; }"
        : "=r"(a) : "l"(p));
    return a;
}
__device__ __forceinline__ void split2h(float a, __half& hi, __half& lo) {
    hi = __float2half_rn(a);
    float r = a - __half2float(hi);      // exact
    lo = __float2half_rn(r * 2048.0f);   // scaled residual, avoids subnormals
}
__device__ __forceinline__ void mma16(float c[4], const uint32_t a[4],
                                      uint32_t b0, uint32_t b1) {
    asm volatile("mma.sync.aligned.m16n8k16.row.col.f32.f16.f16.f32 "
                 "{%0,%1,%2,%3}, {%4,%5,%6,%7}, {%8,%9}, {%0,%1,%2,%3};"
                 : "+f"(c[0]), "+f"(c[1]), "+f"(c[2]), "+f"(c[3])
                 : "r"(a[0]), "r"(a[1]), "r"(a[2]), "r"(a[3]),
                   "r"(b0), "r"(b1));
}
__device__ __forceinline__ void ldsm4(uint32_t& r0, uint32_t& r1,
                                      uint32_t& r2, uint32_t& r3, uint32_t addr) {
    asm volatile("ldmatrix.sync.aligned.m8n8.x4.shared.b16 {%0,%1,%2,%3}, [%4];"
                 : "=r"(r0), "=r"(r1), "=r"(r2), "=r"(r3) : "r"(addr));
}

// ---------------------------------------------------------------------------
// k_init: zero + codebook split + norms from the already-loaded element.
// grid 64 x 512. Block b covers codes b*8..b*8+7 (64 dims each; 2 warps/code).
// ---------------------------------------------------------------------------
__global__ void k_init(const float* __restrict__ emb)
{
    __shared__ float part[16];
    const int t = threadIdx.x;
    const int gid = blockIdx.x * 512 + t;
    const int lane = t & 31, warp = t >> 5;

    float a = emb[gid];
    __half hi, lo;
    split2h(a, hi, lo);
    g_Bh[gid] = hi;
    g_Bl[gid] = lo;
    g_dw[gid] = 0.0f;

    // norm: warp covers 32 dims of one code; 2 warps per code
    float sq = a * a;
#pragma unroll
    for (int o = 16; o; o >>= 1) sq += __shfl_xor_sync(0xffffffffu, sq, o);
    if (lane == 0) part[warp] = sq;
    __syncthreads();
    if (t < 8)
        g_en2[blockIdx.x * 8 + t] = 0.5f * (part[2 * t] + part[2 * t + 1]);

    if (blockIdx.x == 0) {
        g_counts[t] = 0;
        if (t == 0) g_loss = 0.0f;
    }
}

// ---------------------------------------------------------------------------
// k_main: 3-product double-fp16 m16n8k16 + argmin + fused one-hot + dw.
// grid 1024 x 256, 2 blocks/SM. Block: 128 rows x 512 codes, K = 64.
// B fragments double-buffered across the 16 column-steps of each chunk.
// Enc zero-fill issued up-front so DRAM drains during the mma phase.
// argmin over s = 0.5*||e||^2 - dot   (monotone transform of reference score)
// ---------------------------------------------------------------------------
__global__ void __launch_bounds__(256, 2) k_main(const float* __restrict__ flat,
                                                 float* __restrict__ enc)
{
    extern __shared__ __align__(16) unsigned char smx[];
    float* sEn2 = (float*)(smx + OFF_EN);
    int*   sIdx = (int*)(smx + OFF_IDX);

    const int tid  = threadIdx.x;
    const int lane = tid & 31;
    const int w    = tid >> 5;
    const int n0   = blockIdx.x * 128;
    const uint32_t sbase = smem_u32(smx);

    // ---- A fill: fp32 -> (hi, lo') fp16 planes ----
    {
        const float2* f2 = (const float2*)(flat + (size_t)n0 * DDIM);
#pragma unroll
        for (int it = 0; it < 16; it++) {
            int i = it * 256 + tid;          // 4096 half2-slots (128 rows x 32)
            int row = i >> 5, j = i & 31;
            float2 a = f2[i];
            __half hx, lx, hy, ly;
            split2h(a.x, hx, lx);
            split2h(a.y, hy, ly);
            __half2 h; h.x = hx; h.y = hy;
            *(__half2*)(smx + OFF_AH + row * 144 + j * 4) = h;
            h.x = lx; h.y = ly;
            *(__half2*)(smx + OFF_AL + row * 144 + j * 4) = h;
        }
    }

    // ---- early encodings zero-fill: stores drain while we compute ----
    {
        float2* eb = (float2*)(enc + (size_t)n0 * KCODE);
        const float2 z = make_float2(0.0f, 0.0f);
#pragma unroll 8
        for (int it = 0; it < 128; it++)
            eb[it * 256 + tid] = z;          // 32768 float2 = 128 rows x 512
    }

    for (int i = tid; i < KCODE; i += 256) sEn2[i] = g_en2[i];
    __syncthreads();

    // ---- A fragment preload (register-resident): 4 k-steps of 16 ----
    const int r0 = w * 16 + (lane >> 2);
    uint32_t ah[4][4], al[4][4];
#pragma unroll
    for (int ks = 0; ks < 4; ks++) {
        int kb2 = (ks * 16 + (lane & 3) * 2) * 2;   // byte offset within row
        ah[ks][0] = *(const uint32_t*)(smx + OFF_AH + r0 * 144 + kb2);
        ah[ks][1] = *(const uint32_t*)(smx + OFF_AH + (r0 + 8) * 144 + kb2);
        ah[ks][2] = *(const uint32_t*)(smx + OFF_AH + r0 * 144 + kb2 + 16);
        ah[ks][3] = *(const uint32_t*)(smx + OFF_AH + (r0 + 8) * 144 + kb2 + 16);
        al[ks][0] = *(const uint32_t*)(smx + OFF_AL + r0 * 144 + kb2);
        al[ks][1] = *(const uint32_t*)(smx + OFF_AL + (r0 + 8) * 144 + kb2);
        al[ks][2] = *(const uint32_t*)(smx + OFF_AL + r0 * 144 + kb2 + 16);
        al[ks][3] = *(const uint32_t*)(smx + OFF_AL + (r0 + 8) * 144 + kb2 + 16);
    }
    float mn0 = 3.402823466e38f, mn1 = 3.402823466e38f;
    int   mi0 = 0, mi1 = 0;

    const float C1 = 4.8828125e-4f;          // 2^-11

    // per-thread ldmatrix base: code row = lane&7 (stride 144B), kseg = lane>>3
    const uint32_t lmOff = (uint32_t)((lane & 7) * 144 + (lane >> 3) * 16);
    const uint32_t bHbase = sbase + OFF_BH + lmOff;
    const uint32_t bLbase = sbase + OFF_BL + lmOff;

    // ---- main loop: 4 chunks of 128 codes ----
#pragma unroll 1
    for (int c = 0; c < 4; c++) {
        // B chunk fill: 8B copies, padded stride 144B
        {
            const uint2* sh = (const uint2*)(g_Bh + (size_t)c * 128 * 64);
            const uint2* sl = (const uint2*)(g_Bl + (size_t)c * 128 * 64);
#pragma unroll
            for (int it = 0; it < 8; it++) {
                int i = it * 256 + tid;       // 2048 x 8B per plane
                int code = i >> 4, j = i & 15;
                *(uint2*)(smx + OFF_BH + code * 144 + j * 8) = sh[i];
                *(uint2*)(smx + OFF_BL + code * 144 + j * 8) = sl[i];
            }
        }
        __syncthreads();

        // double-buffered B fragments over 16 column-steps (8 codes each)
        uint32_t bh[2][4][2], bl[2][4][2];
        ldsm4(bh[0][0][0], bh[0][0][1], bh[0][1][0], bh[0][1][1], bHbase);
        ldsm4(bh[0][2][0], bh[0][2][1], bh[0][3][0], bh[0][3][1], bHbase + 64);
        ldsm4(bl[0][0][0], bl[0][0][1], bl[0][1][0], bl[0][1][1], bLbase);
        ldsm4(bl[0][2][0], bl[0][2][1], bl[0][3][0], bl[0][3][1], bLbase + 64);

#pragma unroll
        for (int s16 = 0; s16 < 16; s16++) {
            const int cur = s16 & 1, nxt = cur ^ 1;
            if (s16 < 15) {
                const uint32_t nOff = (uint32_t)((s16 + 1) * 1152);  // 8*144
                ldsm4(bh[nxt][0][0], bh[nxt][0][1], bh[nxt][1][0], bh[nxt][1][1],
                      bHbase + nOff);
                ldsm4(bh[nxt][2][0], bh[nxt][2][1], bh[nxt][3][0], bh[nxt][3][1],
                      bHbase + nOff + 64);
                ldsm4(bl[nxt][0][0], bl[nxt][0][1], bl[nxt][1][0], bl[nxt][1][1],
                      bLbase + nOff);
                ldsm4(bl[nxt][2][0], bl[nxt][2][1], bl[nxt][3][0], bl[nxt][3][1],
                      bLbase + nOff + 64);
            }

            float hh[4], m0[4], m1[4];
#pragma unroll
            for (int i = 0; i < 4; i++) { hh[i] = 0.0f; m0[i] = 0.0f; m1[i] = 0.0f; }
#pragma unroll
            for (int ks = 0; ks < 4; ks++) {
                mma16(hh, ah[ks], bh[cur][ks][0], bh[cur][ks][1]);  // hi*hi   (1)
                mma16(m0, ah[ks], bl[cur][ks][0], bl[cur][ks][1]);  // hi*lo'  (2^-11)
                mma16(m1, al[ks], bh[cur][ks][0], bh[cur][ks][1]);  // lo'*hi  (2^-11)
            }

            // epilogue: s = 0.5||e||^2 - dot ; fold into running argmin
            const int cb = c * 128 + s16 * 8 + (lane & 3) * 2;
#pragma unroll
            for (int i = 0; i < 4; i++) {
                float dot = fmaf(C1, m0[i] + m1[i], hh[i]);
                int col = cb + (i & 1);
                float s = __fsub_rn(sEn2[col], dot);
                if (i < 2) { if (s < mn0) { mn0 = s; mi0 = col; } }
                else       { if (s < mn1) { mn1 = s; mi1 = col; } }
            }
        }
        __syncthreads();   // done reading this B chunk
    }

    // ---- cross-lane argmin reduce (4 threads share each row) ----
#pragma unroll
    for (int off = 1; off < 4; off <<= 1) {
        float om = __shfl_xor_sync(0xffffffffu, mn0, off);
        int   oi = __shfl_xor_sync(0xffffffffu, mi0, off);
        if (om < mn0 || (om == mn0 && oi < mi0)) { mn0 = om; mi0 = oi; }
        om = __shfl_xor_sync(0xffffffffu, mn1, off);
        oi = __shfl_xor_sync(0xffffffffu, mi1, off);
        if (om < mn1 || (om == mn1 && oi < mi1)) { mn1 = om; mi1 = oi; }
    }
    if ((lane & 3) == 0) {
        g_idx[n0 + r0] = mi0;     sIdx[r0] = mi0;
        g_idx[n0 + r0 + 8] = mi1; sIdx[r0 + 8] = mi1;
        atomicAdd(&g_counts[mi0], 1);
        atomicAdd(&g_counts[mi1], 1);
    }
    __syncthreads();
    if (tid < 128)
        enc[(size_t)(n0 + tid) * KCODE + sIdx[tid]] = 1.0f;

    // ---- dw segment-sum scatter (coalesced reads, fp atomics) ----
    {
        const float* rowsG = flat + (size_t)n0 * DDIM;
#pragma unroll 4
        for (int it = 0; it < 32; it++) {
            int i = it * 256 + tid;          // 8192 elements
            int r = i >> 6, d = i & 63;
            atomicAdd(&g_dw[sIdx[r] * DDIM + d], rowsG[i]);
        }
    }
}

// ---------------------------------------------------------------------------
// k_update: fused cluster-size smoothing + codebook update + perplexity.
// grid 64 x 512.
// ---------------------------------------------------------------------------
__global__ void k_update(const float* __restrict__ ema_cs,
                         const float* __restrict__ ema_w,
                         float* __restrict__ outP)
{
    __shared__ float red[512];
    __shared__ float scs[512];
    const int t = threadIdx.x;
    float c  = (float)g_counts[t];
    float cs = ema_cs[t] * 0.99f + 0.01f * c;
    red[t] = cs;
    __syncthreads();
    for (int s = 256; s; s >>= 1) { if (t < s) red[t] += red[t + s]; __syncthreads(); }
    float nsum = red[0];
    __syncthreads();
    scs[t] = (cs + 1e-5f) / (nsum + 512.0f * 1e-5f) * nsum;
    __syncthreads();

    const int gid = blockIdx.x * 512 + t;    // 32768 emb elements
    const int k = gid >> 6;
    float wv = ema_w[gid] * 0.99f + 0.01f * g_dw[gid];
    g_new_emb[gid] = wv / scs[k];

    if (blockIdx.x == 0) {
        float p = c * (1.0f / 131072.0f);
        red[t] = p * logf(p + 1e-10f);
        __syncthreads();
        for (int s = 256; s; s >>= 1) { if (t < s) red[t] += red[t + s]; __syncthreads(); }
        if (t == 0) outP[0] = expf(-red[0]);
    }
}

// ---------------------------------------------------------------------------
// k_quant: float4 gather of updated codebook, NHWC->NCHW write, loss partial.
// grid NROWS/128 x 256. Block: 128 rows.
// ---------------------------------------------------------------------------
__global__ __launch_bounds__(256) void k_quant(const float* __restrict__ x,
                                               float* __restrict__ outQ)
{
    __shared__ float q[128][65];
    __shared__ int   idxs[128];
    __shared__ float wsum[8];
    const int t  = threadIdx.x;
    const int n0 = blockIdx.x * 128;
    if (t < 128) idxs[t] = g_idx[n0 + t];
    __syncthreads();

    float lsum = 0.0f;
    const float4* xb4 = (const float4*)(x + (size_t)n0 * DDIM);
    const float4* ne4 = (const float4*)g_new_emb;
#pragma unroll
    for (int it = 0; it < 8; it++) {
        int i = it * 256 + t;                // 2048 float4 = 128 rows x 16
        int r = i >> 4, dg = i & 15;         // dg = dim-group of 4
        float4 qv = ne4[idxs[r] * 16 + dg];  // 16B gather, L2-resident table
        float4 xv = xb4[i];                  // coalesced
        float dx = qv.x - xv.x, dy = qv.y - xv.y;
        float dz = qv.z - xv.z, dw_ = qv.w - xv.w;
        lsum = fmaf(dx, dx, lsum); lsum = fmaf(dy, dy, lsum);
        lsum = fmaf(dz, dz, lsum); lsum = fmaf(dw_, dw_, lsum);
        int d0 = dg << 2;
        q[r][d0] = qv.x; q[r][d0 + 1] = qv.y;
        q[r][d0 + 2] = qv.z; q[r][d0 + 3] = qv.w;
    }
    __syncthreads();

    // NCHW write: rows n0..n0+127 are within one batch image (4096 rows/image)
    const int b   = n0 >> 12;
    const int loc = n0 & 4095;
    float* dst = outQ + (size_t)b * 262144 + loc;
#pragma unroll
    for (int it = 0; it < 32; it++) {
        int i = it * 256 + t;                // 8192 = 64 d x 128 n
        int d = i >> 7, n = i & 127;
        dst[d * 4096 + n] = q[n][d];         // smem read: (65n+d)%32 conflict-free
    }

#pragma unroll
    for (int o = 16; o; o >>= 1) lsum += __shfl_xor_sync(0xffffffffu, lsum, o);
    if ((t & 31) == 0) wsum[t >> 5] = lsum;
    __syncthreads();
    if (t == 0) {
        float s = 0.0f;
#pragma unroll
        for (int wv = 0; wv < 8; wv++) s += wsum[wv];
        atomicAdd(&g_loss, s);
    }
}

__global__ void k_final(float* __restrict__ out0)
{
    out0[0] = 0.25f * g_loss * (1.0f / 8388608.0f);
}

// ---------------------------------------------------------------------------
// Output layout (float32): [0] loss | [1..8388609) quantized NCHW |
// [8388609] perplexity | [8388610..) encodings [131072, 512]
// ---------------------------------------------------------------------------
extern "C" void kernel_launch(void* const* d_in, const int* in_sizes, int n_in,
                              void* d_out, int out_size)
{
    const float* inputs = (const float*)d_in[0];
    const float* emb_w  = (const float*)d_in[1];
    const float* ema_cs = (const float*)d_in[2];
    const float* ema_w  = (const float*)d_in[3];
    float* out  = (float*)d_out;
    float* outQ = out + 1;
    float* outP = out + 1 + 8388608;
    float* outE = out + 2 + 8388608;

    cudaFuncSetAttribute(k_main, cudaFuncAttributeMaxDynamicSharedMemorySize, SMEM_DYN);

    k_init<<<64, 512>>>(emb_w);
    k_main<<<NROWS / 128, 256, SMEM_DYN>>>(inputs, outE);
    k_update<<<64, 512>>>(ema_cs, ema_w, outP);
    k_quant<<<NROWS / 128, 256>>>(inputs, outQ);
    k_final<<<1, 1>>>(out);
}

// round 16
// speedup vs baseline: 1.0413x; 1.0122x over previous
#include <cuda_runtime.h>
#include <cuda_fp16.h>
#include <math.h>
#include <stdint.h>

#define NROWS 131072
#define DDIM  64
#define KCODE 512

// ---- dynamic smem byte offsets for k_main ----
// planes padded to 72 halves (144 B) per row -> 4-bank shift per row/col
#define OFF_AH  0           // 128 rows x 144B
#define OFF_AL  18432
#define OFF_BH  36864       // 128 codes x 144B (one chunk)
#define OFF_BL  55296
#define OFF_EN  73728       // float[512] (0.5*||e||^2)
#define OFF_IDX 75776       // int[128]
#define SMEM_DYN 76288

// ---- static device scratch ----
__device__ __align__(16) __half g_Bh[KCODE * DDIM];   // codebook hi plane
__device__ __align__(16) __half g_Bl[KCODE * DDIM];   // codebook lo' plane
__device__ float  g_en2[KCODE];                       // 0.5*||e||^2
__device__ __align__(16) float g_dw[KCODE * DDIM];
__device__ int    g_counts[KCODE];
__device__ __align__(16) float g_new_emb[KCODE * DDIM];
__device__ int    g_idx[NROWS];
__device__ float  g_loss;
__device__ int    g_done;

// ---- helpers ----
__device__ __forceinline__ uint32_t smem_u32(const void* p) {
    uint32_t a;
    asm("{ .reg .u64 t; cvta.to.shared.u64 t, %1; cvt.u32.u64 %0, t; }"
        : "=r"(a) : "l"(p));
    return a;
}
__device__ __forceinline__ void split2h(float a, __half& hi, __half& lo) {
    hi = __float2half_rn(a);
    float r = a - __half2float(hi);      // exact
    lo = __float2half_rn(r * 2048.0f);   // scaled residual, avoids subnormals
}
__device__ __forceinline__ void mma16(float c[4], const uint32_t a[4],
                                      uint32_t b0, uint32_t b1) {
    asm volatile("mma.sync.aligned.m16n8k16.row.col.f32.f16.f16.f32 "
                 "{%0,%1,%2,%3}, {%4,%5,%6,%7}, {%8,%9}, {%0,%1,%2,%3};"
                 : "+f"(c[0]), "+f"(c[1]), "+f"(c[2]), "+f"(c[3])
                 : "r"(a[0]), "r"(a[1]), "r"(a[2]), "r"(a[3]),
                   "r"(b0), "r"(b1));
}
__device__ __forceinline__ void ldsm4(uint32_t& r0, uint32_t& r1,
                                      uint32_t& r2, uint32_t& r3, uint32_t addr) {
    asm volatile("ldmatrix.sync.aligned.m8n8.x4.shared.b16 {%0,%1,%2,%3}, [%4];"
                 : "=r"(r0), "=r"(r1), "=r"(r2), "=r"(r3) : "r"(addr));
}

// ---------------------------------------------------------------------------
// k_init: zero + codebook split + norms from the already-loaded element.
// grid 64 x 512. Block b covers codes b*8..b*8+7 (64 dims each; 2 warps/code).
// ---------------------------------------------------------------------------
__global__ void k_init(const float* __restrict__ emb)
{
    __shared__ float part[16];
    const int t = threadIdx.x;
    const int gid = blockIdx.x * 512 + t;
    const int lane = t & 31, warp = t >> 5;

    float a = emb[gid];
    __half hi, lo;
    split2h(a, hi, lo);
    g_Bh[gid] = hi;
    g_Bl[gid] = lo;
    g_dw[gid] = 0.0f;

    // norm: warp covers 32 dims of one code; 2 warps per code
    float sq = a * a;
#pragma unroll
    for (int o = 16; o; o >>= 1) sq += __shfl_xor_sync(0xffffffffu, sq, o);
    if (lane == 0) part[warp] = sq;
    __syncthreads();
    if (t < 8)
        g_en2[blockIdx.x * 8 + t] = 0.5f * (part[2 * t] + part[2 * t + 1]);

    if (blockIdx.x == 0) {
        g_counts[t] = 0;
        if (t == 0) { g_loss = 0.0f; g_done = 0; }
    }
}

// ---------------------------------------------------------------------------
// k_main: 3-product double-fp16 m16n8k16 + argmin + fused one-hot + dw.
// grid 1024 x 256, 2 blocks/SM. Block: 128 rows x 512 codes, K = 64.
// B fragments double-buffered across the 16 column-steps of each chunk.
// Enc zero-fill issued up-front so DRAM drains during the mma phase.
// argmin over s = 0.5*||e||^2 - dot   (monotone transform of reference score)
// ---------------------------------------------------------------------------
__global__ void __launch_bounds__(256, 2) k_main(const float* __restrict__ flat,
                                                 float* __restrict__ enc)
{
    extern __shared__ __align__(16) unsigned char smx[];
    float* sEn2 = (float*)(smx + OFF_EN);
    int*   sIdx = (int*)(smx + OFF_IDX);

    const int tid  = threadIdx.x;
    const int lane = tid & 31;
    const int w    = tid >> 5;
    const int n0   = blockIdx.x * 128;
    const uint32_t sbase = smem_u32(smx);

    // ---- A fill: fp32 -> (hi, lo') fp16 planes ----
    {
        const float2* f2 = (const float2*)(flat + (size_t)n0 * DDIM);
#pragma unroll
        for (int it = 0; it < 16; it++) {
            int i = it * 256 + tid;          // 4096 half2-slots (128 rows x 32)
            int row = i >> 5, j = i & 31;
            float2 a = f2[i];
            __half hx, lx, hy, ly;
            split2h(a.x, hx, lx);
            split2h(a.y, hy, ly);
            __half2 h; h.x = hx; h.y = hy;
            *(__half2*)(smx + OFF_AH + row * 144 + j * 4) = h;
            h.x = lx; h.y = ly;
            *(__half2*)(smx + OFF_AL + row * 144 + j * 4) = h;
        }
    }

    // ---- early encodings zero-fill: stores drain while we compute ----
    {
        float2* eb = (float2*)(enc + (size_t)n0 * KCODE);
        const float2 z = make_float2(0.0f, 0.0f);
#pragma unroll 8
        for (int it = 0; it < 128; it++)
            eb[it * 256 + tid] = z;          // 32768 float2 = 128 rows x 512
    }

    for (int i = tid; i < KCODE; i += 256) sEn2[i] = g_en2[i];
    __syncthreads();

    // ---- A fragment preload (register-resident): 4 k-steps of 16 ----
    const int r0 = w * 16 + (lane >> 2);
    uint32_t ah[4][4], al[4][4];
#pragma unroll
    for (int ks = 0; ks < 4; ks++) {
        int kb2 = (ks * 16 + (lane & 3) * 2) * 2;   // byte offset within row
        ah[ks][0] = *(const uint32_t*)(smx + OFF_AH + r0 * 144 + kb2);
        ah[ks][1] = *(const uint32_t*)(smx + OFF_AH + (r0 + 8) * 144 + kb2);
        ah[ks][2] = *(const uint32_t*)(smx + OFF_AH + r0 * 144 + kb2 + 16);
        ah[ks][3] = *(const uint32_t*)(smx + OFF_AH + (r0 + 8) * 144 + kb2 + 16);
        al[ks][0] = *(const uint32_t*)(smx + OFF_AL + r0 * 144 + kb2);
        al[ks][1] = *(const uint32_t*)(smx + OFF_AL + (r0 + 8) * 144 + kb2);
        al[ks][2] = *(const uint32_t*)(smx + OFF_AL + r0 * 144 + kb2 + 16);
        al[ks][3] = *(const uint32_t*)(smx + OFF_AL + (r0 + 8) * 144 + kb2 + 16);
    }
    float mn0 = 3.402823466e38f, mn1 = 3.402823466e38f;
    int   mi0 = 0, mi1 = 0;

    const float C1 = 4.8828125e-4f;          // 2^-11

    // per-thread ldmatrix base: code row = lane&7 (stride 144B), kseg = lane>>3
    const uint32_t lmOff = (uint32_t)((lane & 7) * 144 + (lane >> 3) * 16);
    const uint32_t bHbase = sbase + OFF_BH + lmOff;
    const uint32_t bLbase = sbase + OFF_BL + lmOff;

    // ---- main loop: 4 chunks of 128 codes ----
#pragma unroll 1
    for (int c = 0; c < 4; c++) {
        // B chunk fill: 8B copies, padded stride 144B
        {
            const uint2* sh = (const uint2*)(g_Bh + (size_t)c * 128 * 64);
            const uint2* sl = (const uint2*)(g_Bl + (size_t)c * 128 * 64);
#pragma unroll
            for (int it = 0; it < 8; it++) {
                int i = it * 256 + tid;       // 2048 x 8B per plane
                int code = i >> 4, j = i & 15;
                *(uint2*)(smx + OFF_BH + code * 144 + j * 8) = sh[i];
                *(uint2*)(smx + OFF_BL + code * 144 + j * 8) = sl[i];
            }
        }
        __syncthreads();

        // double-buffered B fragments over 16 column-steps (8 codes each)
        uint32_t bh[2][4][2], bl[2][4][2];
        ldsm4(bh[0][0][0], bh[0][0][1], bh[0][1][0], bh[0][1][1], bHbase);
        ldsm4(bh[0][2][0], bh[0][2][1], bh[0][3][0], bh[0][3][1], bHbase + 64);
        ldsm4(bl[0][0][0], bl[0][0][1], bl[0][1][0], bl[0][1][1], bLbase);
        ldsm4(bl[0][2][0], bl[0][2][1], bl[0][3][0], bl[0][3][1], bLbase + 64);

#pragma unroll
        for (int s16 = 0; s16 < 16; s16++) {
            const int cur = s16 & 1, nxt = cur ^ 1;
            if (s16 < 15) {
                const uint32_t nOff = (uint32_t)((s16 + 1) * 1152);  // 8*144
                ldsm4(bh[nxt][0][0], bh[nxt][0][1], bh[nxt][1][0], bh[nxt][1][1],
                      bHbase + nOff);
                ldsm4(bh[nxt][2][0], bh[nxt][2][1], bh[nxt][3][0], bh[nxt][3][1],
                      bHbase + nOff + 64);
                ldsm4(bl[nxt][0][0], bl[nxt][0][1], bl[nxt][1][0], bl[nxt][1][1],
                      bLbase + nOff);
                ldsm4(bl[nxt][2][0], bl[nxt][2][1], bl[nxt][3][0], bl[nxt][3][1],
                      bLbase + nOff + 64);
            }

            float hh[4], m0[4], m1[4];
#pragma unroll
            for (int i = 0; i < 4; i++) { hh[i] = 0.0f; m0[i] = 0.0f; m1[i] = 0.0f; }
#pragma unroll
            for (int ks = 0; ks < 4; ks++) {
                mma16(hh, ah[ks], bh[cur][ks][0], bh[cur][ks][1]);  // hi*hi   (1)
                mma16(m0, ah[ks], bl[cur][ks][0], bl[cur][ks][1]);  // hi*lo'  (2^-11)
                mma16(m1, al[ks], bh[cur][ks][0], bh[cur][ks][1]);  // lo'*hi  (2^-11)
            }

            // epilogue: s = 0.5||e||^2 - dot ; fold into running argmin
            const int cb = c * 128 + s16 * 8 + (lane & 3) * 2;
#pragma unroll
            for (int i = 0; i < 4; i++) {
                float dot = fmaf(C1, m0[i] + m1[i], hh[i]);
                int col = cb + (i & 1);
                float s = __fsub_rn(sEn2[col], dot);
                if (i < 2) { if (s < mn0) { mn0 = s; mi0 = col; } }
                else       { if (s < mn1) { mn1 = s; mi1 = col; } }
            }
        }
        __syncthreads();   // done reading this B chunk
    }

    // ---- cross-lane argmin reduce (4 threads share each row) ----
#pragma unroll
    for (int off = 1; off < 4; off <<= 1) {
        float om = __shfl_xor_sync(0xffffffffu, mn0, off);
        int   oi = __shfl_xor_sync(0xffffffffu, mi0, off);
        if (om < mn0 || (om == mn0 && oi < mi0)) { mn0 = om; mi0 = oi; }
        om = __shfl_xor_sync(0xffffffffu, mn1, off);
        oi = __shfl_xor_sync(0xffffffffu, mi1, off);
        if (om < mn1 || (om == mn1 && oi < mi1)) { mn1 = om; mi1 = oi; }
    }
    if ((lane & 3) == 0) {
        g_idx[n0 + r0] = mi0;     sIdx[r0] = mi0;
        g_idx[n0 + r0 + 8] = mi1; sIdx[r0 + 8] = mi1;
        atomicAdd(&g_counts[mi0], 1);
        atomicAdd(&g_counts[mi1], 1);
    }
    __syncthreads();
    if (tid < 128)
        enc[(size_t)(n0 + tid) * KCODE + sIdx[tid]] = 1.0f;

    // ---- dw segment-sum scatter (coalesced reads, fp atomics) ----
    {
        const float* rowsG = flat + (size_t)n0 * DDIM;
#pragma unroll 4
        for (int it = 0; it < 32; it++) {
            int i = it * 256 + tid;          // 8192 elements
            int r = i >> 6, d = i & 63;
            atomicAdd(&g_dw[sIdx[r] * DDIM + d], rowsG[i]);
        }
    }
}

// ---------------------------------------------------------------------------
// k_update: fused cluster-size smoothing + codebook update + perplexity.
// grid 64 x 512.
// ---------------------------------------------------------------------------
__global__ void k_update(const float* __restrict__ ema_cs,
                         const float* __restrict__ ema_w,
                         float* __restrict__ outP)
{
    __shared__ float red[512];
    __shared__ float scs[512];
    const int t = threadIdx.x;
    float c  = (float)g_counts[t];
    float cs = ema_cs[t] * 0.99f + 0.01f * c;
    red[t] = cs;
    __syncthreads();
    for (int s = 256; s; s >>= 1) { if (t < s) red[t] += red[t + s]; __syncthreads(); }
    float nsum = red[0];
    __syncthreads();
    scs[t] = (cs + 1e-5f) / (nsum + 512.0f * 1e-5f) * nsum;
    __syncthreads();

    const int gid = blockIdx.x * 512 + t;    // 32768 emb elements
    const int k = gid >> 6;
    float wv = ema_w[gid] * 0.99f + 0.01f * g_dw[gid];
    g_new_emb[gid] = wv / scs[k];

    if (blockIdx.x == 0) {
        float p = c * (1.0f / 131072.0f);
        red[t] = p * logf(p + 1e-10f);
        __syncthreads();
        for (int s = 256; s; s >>= 1) { if (t < s) red[t] += red[t + s]; __syncthreads(); }
        if (t == 0) outP[0] = expf(-red[0]);
    }
}

// ---------------------------------------------------------------------------
// k_quant: batched float4 gather of updated codebook, NHWC->NCHW write,
// loss partial, fused final-loss via done-counter (last block writes out[0]).
// grid NROWS/128 x 256. Block: 128 rows.
// Phase 1 issues all 16 float4 loads before any consumer (MLP ~16).
// ---------------------------------------------------------------------------
__global__ __launch_bounds__(256) void k_quant(const float* __restrict__ x,
                                               float* __restrict__ outQ,
                                               float* __restrict__ out0)
{
    __shared__ float q[128][65];
    __shared__ int   idxs[128];
    __shared__ float wsum[8];
    const int t  = threadIdx.x;
    const int n0 = blockIdx.x * 128;
    if (t < 128) idxs[t] = g_idx[n0 + t];
    __syncthreads();

    const float4* xb4 = (const float4*)(x + (size_t)n0 * DDIM);
    const float4* ne4 = (const float4*)g_new_emb;

    // ---- phase 1: issue ALL loads into register arrays (MLP ~16) ----
    float4 qv[8], xv[8];
#pragma unroll
    for (int it = 0; it < 8; it++) {
        int i = it * 256 + t;                // 2048 float4 = 128 rows x 16
        int r = i >> 4, dg = i & 15;
        qv[it] = ne4[idxs[r] * 16 + dg];     // 16B gather, L2-resident table
        xv[it] = xb4[i];                     // coalesced
    }

    // ---- phase 2: loss + smem transpose stores ----
    float lsum = 0.0f;
#pragma unroll
    for (int it = 0; it < 8; it++) {
        int i = it * 256 + t;
        int r = i >> 4, dg = i & 15;
        float dx = qv[it].x - xv[it].x, dy = qv[it].y - xv[it].y;
        float dz = qv[it].z - xv[it].z, dw_ = qv[it].w - xv[it].w;
        lsum = fmaf(dx, dx, lsum); lsum = fmaf(dy, dy, lsum);
        lsum = fmaf(dz, dz, lsum); lsum = fmaf(dw_, dw_, lsum);
        int d0 = dg << 2;
        q[r][d0] = qv[it].x; q[r][d0 + 1] = qv[it].y;
        q[r][d0 + 2] = qv[it].z; q[r][d0 + 3] = qv[it].w;
    }
    __syncthreads();

    // NCHW write: rows n0..n0+127 are within one batch image (4096 rows/image)
    const int b   = n0 >> 12;
    const int loc = n0 & 4095;
    float* dst = outQ + (size_t)b * 262144 + loc;
#pragma unroll
    for (int it = 0; it < 32; it++) {
        int i = it * 256 + t;                // 8192 = 64 d x 128 n
        int d = i >> 7, n = i & 127;
        dst[d * 4096 + n] = q[n][d];         // smem read: (65n+d)%32 conflict-free
    }

#pragma unroll
    for (int o = 16; o; o >>= 1) lsum += __shfl_xor_sync(0xffffffffu, lsum, o);
    if ((t & 31) == 0) wsum[t >> 5] = lsum;
    __syncthreads();
    if (t == 0) {
        float s = 0.0f;
#pragma unroll
        for (int wv2 = 0; wv2 < 8; wv2++) s += wsum[wv2];
        atomicAdd(&g_loss, s);

        // last block to finish publishes the final loss
        __threadfence();
        int old = atomicAdd(&g_done, 1);
        if (old == 1023) {
            __threadfence();
            float gl = *(volatile float*)&g_loss;
            out0[0] = 0.25f * gl * (1.0f / 8388608.0f);
        }
    }
}

// ---------------------------------------------------------------------------
// Output layout (float32): [0] loss | [1..8388609) quantized NCHW |
// [8388609] perplexity | [8388610..) encodings [131072, 512]
// ---------------------------------------------------------------------------
extern "C" void kernel_launch(void* const* d_in, const int* in_sizes, int n_in,
                              void* d_out, int out_size)
{
    const float* inputs = (const float*)d_in[0];
    const float* emb_w  = (const float*)d_in[1];
    const float* ema_cs = (const float*)d_in[2];
    const float* ema_w  = (const float*)d_in[3];
    float* out  = (float*)d_out;
    float* outQ = out + 1;
    float* outP = out + 1 + 8388608;
    float* outE = out + 2 + 8388608;

    cudaFuncSetAttribute(k_main, cudaFuncAttributeMaxDynamicSharedMemorySize, SMEM_DYN);

    k_init<<<64, 512>>>(emb_w);
    k_main<<<NROWS / 128, 256, SMEM_DYN>>>(inputs, outE);
    k_update<<<64, 512>>>(ema_cs, ema_w, outP);
    k_quant<<<NROWS / 128, 256>>>(inputs, outQ, out);
}